// round 14
// baseline (speedup 1.0000x reference)
#include <cuda_runtime.h>
#include <cuda_fp16.h>
#include <cstdint>

// ---------------------------------------------------------------------------
// PAC transposed conv via warp-level tensor cores (mma.sync, baseline PTX).
// R13 = R12 + shared raw-B fragments for kw in {0,1} (same dj=0 shift):
// per kh, B is loaded once and scaled by two kern values into two taps.
// For output (h,w): valid taps (kh,kw) have (h+kh) odd & (w+kw) odd.
// Per tap t, shift (di,dj)=(kh>>1,kw>>1):
//   D[o,px] += sum_c W[o,c,t] * (kern_t[px] * x[c, qy+di, qx+dj])
//   out[o, 2qy+cy, 2qx+cx] = bias[o] + D_{cy,cx}[o,px]
// kern_t = exp(-0.5*sum_g (guide[g,h+kh-1,w+kw-1]-guide[g,h,w])^2), 0-pad.
// CTA tile: 8x16 quads (px = qy*16+qx, 128 px), o = 64. 512 CTAs.
// ---------------------------------------------------------------------------

constexpr int SMX  = 0;                   // X: [y9][x17] rows of 144B = 22032
constexpr int SMW  = 22032;               // W: 9 taps, padded stride
constexpr int TAPS = 9360;                // 65*144: tap t at bank shift 4t
constexpr int SMK  = SMW + 9 * TAPS;      // 106272 ; kern [9][128] dup-half2
constexpr int SMEM_TOTAL = SMK + 1152 * 4;   // 110880 B

__device__ __forceinline__ uint32_t s2u(const void* p) {
    uint32_t a;
    asm("{ .reg .u64 t; cvta.to.shared.u64 t, %1; cvt.u32.u64 %0, t; }"
        : "=r"(a) : "l"(p));
    return a;
}
__device__ __forceinline__ void ldmx4(uint32_t* r, uint32_t addr) {
    asm volatile("ldmatrix.sync.aligned.m8n8.x4.shared.b16 {%0,%1,%2,%3}, [%4];"
                 : "=r"(r[0]), "=r"(r[1]), "=r"(r[2]), "=r"(r[3]) : "r"(addr));
}
__device__ __forceinline__ void ldmx2(uint32_t& r0, uint32_t& r1, uint32_t addr) {
    asm volatile("ldmatrix.sync.aligned.m8n8.x2.shared.b16 {%0,%1}, [%2];"
                 : "=r"(r0), "=r"(r1) : "r"(addr));
}
__device__ __forceinline__ void mma16816(float& d0, float& d1, float& d2, float& d3,
                                         const uint32_t* a, uint32_t b0, uint32_t b1) {
    asm volatile(
        "mma.sync.aligned.m16n8k16.row.col.f32.f16.f16.f32 "
        "{%0,%1,%2,%3}, {%4,%5,%6,%7}, {%8,%9}, {%0,%1,%2,%3};"
        : "+f"(d0), "+f"(d1), "+f"(d2), "+f"(d3)
        : "r"(a[0]), "r"(a[1]), "r"(a[2]), "r"(a[3]), "r"(b0), "r"(b1));
}
__device__ __forceinline__ uint32_t hmul2u(uint32_t a, uint32_t b) {
    __half2 r = __hmul2(*(__half2*)&a, *(__half2*)&b);
    return *(uint32_t*)&r;
}

__global__ void __launch_bounds__(512, 2)
pac_hmma(const float* __restrict__ x, const float* __restrict__ g,
         const float* __restrict__ wgt, const float* __restrict__ bias,
         float* __restrict__ out)
{
    extern __shared__ char sm[];
    const uint32_t smb = s2u(sm);
    const int tid = threadIdx.x;

    const int b   = blockIdx.x >> 7;     // 4 batches
    const int tl  = blockIdx.x & 127;
    const int Ty0 = (tl >> 3) * 8;       // quad-row origin (tile 8 rows)
    const int Tx0 = (tl & 7) * 16;       // quad-col origin (tile 16 cols)

    // --- stage X: [y 0..8][x 0..16][64 c] fp16, 144B rows, zero halo
    const float* xb = x + b * 64 * 128 * 128;
    for (int i = tid; i < 153 * 32; i += 512) {
        int xc = i % 17;
        int yc = i / 17;
        int y  = yc % 9, c2 = yc / 9;
        int gy = Ty0 + y, gx = Tx0 + xc;
        __half2 v = __floats2half2_rn(0.f, 0.f);
        if (gy < 128 && gx < 128)
            v = __floats2half2_rn(xb[((2 * c2) * 128 + gy) * 128 + gx],
                                  xb[((2 * c2 + 1) * 128 + gy) * 128 + gx]);
        *(__half2*)(sm + SMX + (y * 17 + xc) * 144 + c2 * 4) = v;
    }
    // --- stage W: linear (coalesced) read, scatter STS.16 into [t][o][c]
    for (int i = tid; i < 36864; i += 512) {
        int t  = i % 9;
        int oc = i / 9;
        int o  = oc & 63, c = oc >> 6;
        *(__half*)(sm + SMW + t * TAPS + o * 144 + c * 2) =
            __float2half_rn(wgt[i]);
    }
    // --- stage kern: [tap 9][px 128], stored as duplicated half2 (uint32)
    {
        const float* gb = g + b * 3 * 65536;
        uint32_t* kernS = (uint32_t*)(sm + SMK);
        for (int v = tid; v < 1152; v += 512) {
            int t  = v >> 7, px = v & 127;
            int qy = px >> 4, qx = px & 15;
            int kh = t / 3, kw = t - kh * 3;
            int cy = 1 - (kh & 1), cx = 1 - (kw & 1);
            int h  = 2 * (Ty0 + qy) + cy;
            int w  = 2 * (Tx0 + qx) + cx;
            int yy = h + kh - 1, xx = w + kw - 1;
            bool inb = ((unsigned)yy < 256u) & ((unsigned)xx < 256u);
            float s = 0.f;
            #pragma unroll
            for (int gg = 0; gg < 3; ++gg) {
                float gc = __ldg(&gb[gg * 65536 + h * 256 + w]);
                float gn = inb ? __ldg(&gb[gg * 65536 + yy * 256 + xx]) : 0.f;
                float d = gn - gc;
                s = fmaf(d, d, s);
            }
            __half2 hv = __float2half2_rn(__expf(-0.5f * s));
            kernS[v] = *(uint32_t*)&hv;
        }
    }
    __syncthreads();

    // warp tiling: mblk -> 16 o rows ; nq -> 32 px (2 quad-rows)
    const int wid  = tid >> 5, lane = tid & 31;
    const int mblk = wid >> 2, nq = wid & 3;
    const int ob   = mblk * 16;
    const int gq   = lane >> 2, t4 = lane & 3;   // D rows gq,gq+8; cols 2t4,2t4+1

    // A ldmatrix lane address (row-major A, x4: o rows | o+8 rows, 2 k-halves)
    const int a_orow = ob + (lane & 7) + ((lane >> 3) & 1) * 8;
    const uint32_t aoff = smb + SMW + (uint32_t)(a_orow * 144 + (lane >> 4) * 16);
    // B ldmx2 lane address pieces
    const int bj   = lane & 7;
    const int bmat = (lane >> 3) & 1;
    // B base for nb=0 (nb adds compile-time constants)
    const uint32_t bbase0 =
        smb + SMX + (uint32_t)(((2 * nq) * 17 + bj) * 144 + bmat * 16);
    const uint32_t* kbase = (const uint32_t*)(sm + SMK) + nq * 32 + (lane >> 2);

    const float bias_lo = __ldg(&bias[ob + gq]);
    const float bias_hi = __ldg(&bias[ob + gq + 8]);
    float* obase = out + (size_t)b * 64 * 65536;

    #pragma unroll
    for (int grp = 0; grp < 2; ++grp) {
        float acc[2][16];
        #pragma unroll
        for (int c2 = 0; c2 < 2; ++c2)
            #pragma unroll
            for (int e = 0; e < 16; ++e) acc[c2][e] = 0.f;

        const int kh0 = grp ? 0 : 1;
        const int khs = grp ? 2 : 3;

        #pragma unroll 1
        for (int kh = kh0; kh < 3; kh += khs) {
            const int t0 = kh * 3;             // kw=0 tap (-> acc[1])
            const int di = kh >> 1;
            const uint32_t ab0 = aoff + (uint32_t)(t0 * TAPS);
            const uint32_t bd  = bbase0 + (uint32_t)((di * 17) * 144);
            const uint32_t* kt = kbase + t0 * 128;

            // --- fused pass: kw=0 and kw=1 share raw B (dj=0) ---
            {
                uint32_t k0[4], k1[4];
                #pragma unroll
                for (int nb = 0; nb < 4; ++nb) {
                    const int ko = (nb >> 1) * 16 + (nb & 1) * 8;
                    k0[nb] = kt[ko];           // kern tap (kh,0)
                    k1[nb] = kt[128 + ko];     // kern tap (kh,1)
                }
                #pragma unroll
                for (int kb = 0; kb < 4; ++kb) {
                    uint32_t A0[4], A1[4];
                    ldmx4(A0, ab0 + (uint32_t)(kb * 32));
                    ldmx4(A1, ab0 + (uint32_t)(TAPS + kb * 32));
                    #pragma unroll
                    for (int nb = 0; nb < 4; ++nb) {
                        const uint32_t bofs =
                            (uint32_t)(((nb >> 1) * 17 + (nb & 1) * 8) * 144 + kb * 32);
                        uint32_t r0, r1;
                        ldmx2(r0, r1, bd + bofs);
                        uint32_t b0 = hmul2u(r0, k0[nb]);
                        uint32_t b1 = hmul2u(r1, k0[nb]);
                        mma16816(acc[1][nb * 4 + 0], acc[1][nb * 4 + 1],
                                 acc[1][nb * 4 + 2], acc[1][nb * 4 + 3],
                                 A0, b0, b1);
                        b0 = hmul2u(r0, k1[nb]);
                        b1 = hmul2u(r1, k1[nb]);
                        mma16816(acc[0][nb * 4 + 0], acc[0][nb * 4 + 1],
                                 acc[0][nb * 4 + 2], acc[0][nb * 4 + 3],
                                 A1, b0, b1);
                    }
                }
            }
            // --- kw=2 pass: dj=1, own B (-> acc[1]) ---
            {
                uint32_t k2[4];
                #pragma unroll
                for (int nb = 0; nb < 4; ++nb)
                    k2[nb] = kt[256 + (nb >> 1) * 16 + (nb & 1) * 8];
                #pragma unroll
                for (int kb = 0; kb < 4; ++kb) {
                    uint32_t A2[4];
                    ldmx4(A2, ab0 + (uint32_t)(2 * TAPS + kb * 32));
                    #pragma unroll
                    for (int nb = 0; nb < 4; ++nb) {
                        const uint32_t bofs =
                            (uint32_t)(((nb >> 1) * 17 + (nb & 1) * 8) * 144 + kb * 32);
                        uint32_t r0, r1;
                        ldmx2(r0, r1, bd + 144 + bofs);   // dj=1
                        uint32_t b0 = hmul2u(r0, k2[nb]);
                        uint32_t b1 = hmul2u(r1, k2[nb]);
                        mma16816(acc[1][nb * 4 + 0], acc[1][nb * 4 + 1],
                                 acc[1][nb * 4 + 2], acc[1][nb * 4 + 3],
                                 A2, b0, b1);
                    }
                }
            }
        }

        // store strips for cy = grp
        #pragma unroll
        for (int nb = 0; nb < 4; ++nb) {
            const int qy = 2 * nq + (nb >> 1);
            const int qx = (nb & 1) * 8 + 2 * t4;
            const int h  = 2 * (Ty0 + qy) + grp;
            const int w0 = 2 * (Tx0 + qx);
            #pragma unroll
            for (int rh = 0; rh < 2; ++rh) {
                const int o  = ob + gq + rh * 8;
                const float bv = rh ? bias_hi : bias_lo;
                float4 v = make_float4(acc[0][nb * 4 + rh * 2]     + bv,
                                       acc[1][nb * 4 + rh * 2]     + bv,
                                       acc[0][nb * 4 + rh * 2 + 1] + bv,
                                       acc[1][nb * 4 + rh * 2 + 1] + bv);
                *(float4*)&obase[((size_t)o * 256 + h) * 256 + w0] = v;
            }
        }
    }
}

extern "C" void kernel_launch(void* const* d_in, const int* in_sizes, int n_in,
                              void* d_out, int out_size) {
    const float* x      = (const float*)d_in[0];
    const float* guide  = (const float*)d_in[1];
    const float* weight = (const float*)d_in[2];
    const float* bias   = (const float*)d_in[3];
    float* out = (float*)d_out;

    cudaFuncSetAttribute(pac_hmma, cudaFuncAttributeMaxDynamicSharedMemorySize,
                         SMEM_TOTAL);
    // 4 batches * 128 tiles (8x16 quads each) = 512 CTAs
    pac_hmma<<<512, 512, SMEM_TOTAL>>>(x, guide, weight, bias, out);
}

// round 15
// speedup vs baseline: 1.1712x; 1.1712x over previous
#include <cuda_runtime.h>
#include <cuda_fp16.h>
#include <cstdint>

// ---------------------------------------------------------------------------
// PAC transposed conv via warp-level tensor cores (mma.sync, baseline PTX).
// R14 = R12 hot loop (51.9us) + pre-kernel that pre-transposes W and X into
// device-global fp16 buffers so per-CTA staging is pure vectorized copy.
// For output (h,w): valid taps (kh,kw) have (h+kh) odd & (w+kw) odd.
// Per tap t, shift (di,dj)=(kh>>1,kw>>1):
//   D[o,px] += sum_c W[o,c,t] * (kern_t[px] * x[c, qy+di, qx+dj])
//   out[o, 2qy+cy, 2qx+cx] = bias[o] + D_{cy,cx}[o,px]
// kern_t = exp(-0.5*sum_g (guide[g,h+kh-1,w+kw-1]-guide[g,h,w])^2), 0-pad.
// CTA tile: 8x16 quads (px = qy*16+qx, 128 px), o = 64. 512 CTAs.
// ---------------------------------------------------------------------------

constexpr int SMX  = 0;                   // X: [y9][x17] rows of 144B = 22032
constexpr int SMW  = 22032;               // W: 9 taps, padded stride
constexpr int TAPS = 9360;                // 65*144: tap t at bank shift 4t
constexpr int SMK  = SMW + 9 * TAPS;      // 106272 ; kern [9][128] dup-half2
constexpr int SMEM_TOTAL = SMK + 1152 * 4;   // 110880 B

// device-global staging buffers (written by pac_pre each launch)
__device__ __align__(16) __half g_xh[4u * 128 * 128 * 64];  // [b][y][x][c] fp16
__device__ __align__(16) __half g_wh[9 * 4680];             // smem image of W

__device__ __forceinline__ uint32_t s2u(const void* p) {
    uint32_t a;
    asm("{ .reg .u64 t; cvta.to.shared.u64 t, %1; cvt.u32.u64 %0, t; }"
        : "=r"(a) : "l"(p));
    return a;
}
__device__ __forceinline__ void ldmx4(uint32_t* r, uint32_t addr) {
    asm volatile("ldmatrix.sync.aligned.m8n8.x4.shared.b16 {%0,%1,%2,%3}, [%4];"
                 : "=r"(r[0]), "=r"(r[1]), "=r"(r[2]), "=r"(r[3]) : "r"(addr));
}
__device__ __forceinline__ void ldmx2(uint32_t& r0, uint32_t& r1, uint32_t addr) {
    asm volatile("ldmatrix.sync.aligned.m8n8.x2.shared.b16 {%0,%1}, [%2];"
                 : "=r"(r0), "=r"(r1) : "r"(addr));
}
__device__ __forceinline__ void mma16816(float& d0, float& d1, float& d2, float& d3,
                                         const uint32_t* a, uint32_t b0, uint32_t b1) {
    asm volatile(
        "mma.sync.aligned.m16n8k16.row.col.f32.f16.f16.f32 "
        "{%0,%1,%2,%3}, {%4,%5,%6,%7}, {%8,%9}, {%0,%1,%2,%3};"
        : "+f"(d0), "+f"(d1), "+f"(d2), "+f"(d3)
        : "r"(a[0]), "r"(a[1]), "r"(a[2]), "r"(a[3]), "r"(b0), "r"(b1));
}
__device__ __forceinline__ uint32_t hmul2u(uint32_t a, uint32_t b) {
    __half2 r = __hmul2(*(__half2*)&a, *(__half2*)&b);
    return *(uint32_t*)&r;
}

// ---------------------------------------------------------------------------
// Pre-kernel: CTAs 0..511 transpose x (b,y) slices into g_xh [b][y][x][c];
//             CTAs 512..543 build the padded fp16 W image in g_wh.
// ---------------------------------------------------------------------------
__global__ void __launch_bounds__(512)
pac_pre(const float* __restrict__ x, const float* __restrict__ wgt)
{
    const int blk = blockIdx.x, tid = threadIdx.x;
    if (blk < 512) {
        __shared__ __align__(16) __half tb[128 * 66];   // [x][c] padded
        const int b = blk >> 7, y = blk & 127;
        const float* xin = x + ((size_t)b * 64 * 128 + y) * 128;
        #pragma unroll
        for (int k = 0; k < 16; ++k) {
            int c  = k * 4 + (tid >> 7);
            int xx = tid & 127;
            tb[xx * 66 + c] = __float2half_rn(xin[(size_t)c * 16384 + xx]);
        }
        __syncthreads();
        __half* outp = g_xh + ((size_t)(b * 128 + y) * 128) * 64;
        #pragma unroll
        for (int v = 0; v < 2; ++v) {
            int j  = (tid * 2 + v) * 8;      // 8 halves per store
            int xx = j >> 6, c0 = j & 63;
            const uint32_t* src =
                (const uint32_t*)((const char*)tb + xx * 132 + c0 * 2);
            uint4 val = make_uint4(src[0], src[1], src[2], src[3]);
            *(uint4*)(outp + j) = val;
        }
    } else {
        const int i0 = (blk - 512) * 1152;
        #pragma unroll
        for (int k = 0; k < 3; ++k) {
            int i = i0 + k * 512 + tid;
            if (i < i0 + 1152) {
                int t  = i % 9;
                int oc = i / 9;
                int o  = oc & 63, c = oc >> 6;
                g_wh[t * 4680 + o * 72 + c] = __float2half_rn(wgt[i]);
            }
        }
    }
}

__global__ void __launch_bounds__(512, 2)
pac_hmma(const float* __restrict__ g, const float* __restrict__ bias,
         float* __restrict__ out)
{
    extern __shared__ char sm[];
    const uint32_t smb = s2u(sm);
    const int tid = threadIdx.x;

    const int b   = blockIdx.x >> 7;     // 4 batches
    const int tl  = blockIdx.x & 127;
    const int Ty0 = (tl >> 3) * 8;       // quad-row origin (tile 8 rows)
    const int Tx0 = (tl & 7) * 16;       // quad-col origin (tile 16 cols)

    // --- stage X: rows (y,xc) copied 16B-wise from pre-transposed g_xh
    const __half* xg = g_xh + (size_t)b * 128 * 128 * 64;
    for (int i = tid; i < 1224; i += 512) {     // 153 rows * 8 vec4
        int r = i >> 3, v = i & 7;
        int y = r / 17, xc = r - y * 17;
        int gy = Ty0 + y, gx = Tx0 + xc;
        uint4 val = make_uint4(0u, 0u, 0u, 0u);
        if (gy < 128 && gx < 128)
            val = *(const uint4*)(xg + (size_t)((gy * 128 + gx) << 6) + v * 8);
        *(uint4*)(sm + SMX + r * 144 + v * 16) = val;
    }
    // --- stage W: flat vectorized copy of the prebuilt padded image
    {
        const uint4* wsrc = (const uint4*)g_wh;     // 84240 B = 5265 vec4
        for (int i = tid; i < 5265; i += 512)
            *(uint4*)(sm + SMW + i * 16) = wsrc[i];
    }
    // --- stage kern: [tap 9][px 128], stored as duplicated half2 (uint32)
    {
        const float* gb = g + b * 3 * 65536;
        uint32_t* kernS = (uint32_t*)(sm + SMK);
        for (int v = tid; v < 1152; v += 512) {
            int t  = v >> 7, px = v & 127;
            int qy = px >> 4, qx = px & 15;
            int kh = t / 3, kw = t - kh * 3;
            int cy = 1 - (kh & 1), cx = 1 - (kw & 1);
            int h  = 2 * (Ty0 + qy) + cy;
            int w  = 2 * (Tx0 + qx) + cx;
            int yy = h + kh - 1, xx = w + kw - 1;
            bool inb = ((unsigned)yy < 256u) & ((unsigned)xx < 256u);
            float s = 0.f;
            #pragma unroll
            for (int gg = 0; gg < 3; ++gg) {
                float gc = __ldg(&gb[gg * 65536 + h * 256 + w]);
                float gn = inb ? __ldg(&gb[gg * 65536 + yy * 256 + xx]) : 0.f;
                float d = gn - gc;
                s = fmaf(d, d, s);
            }
            __half2 hv = __float2half2_rn(__expf(-0.5f * s));
            kernS[v] = *(uint32_t*)&hv;
        }
    }
    __syncthreads();

    // warp tiling: mblk -> 16 o rows ; nq -> 32 px (2 quad-rows)
    const int wid  = tid >> 5, lane = tid & 31;
    const int mblk = wid >> 2, nq = wid & 3;
    const int ob   = mblk * 16;
    const int gq   = lane >> 2, t4 = lane & 3;   // D rows gq,gq+8; cols 2t4,2t4+1

    // A ldmatrix lane address (row-major A, x4: o rows | o+8 rows, 2 k-halves)
    const int a_orow = ob + (lane & 7) + ((lane >> 3) & 1) * 8;
    const uint32_t aoff = smb + SMW + (uint32_t)(a_orow * 144 + (lane >> 4) * 16);
    // B ldmx2 lane address pieces
    const int bj   = lane & 7;
    const int bmat = (lane >> 3) & 1;
    // B base for nb=0 (nb adds compile-time constants)
    const uint32_t bbase0 =
        smb + SMX + (uint32_t)(((2 * nq) * 17 + bj) * 144 + bmat * 16);
    const uint32_t* kbase = (const uint32_t*)(sm + SMK) + nq * 32 + (lane >> 2);

    const float bias_lo = __ldg(&bias[ob + gq]);
    const float bias_hi = __ldg(&bias[ob + gq + 8]);
    float* obase = out + (size_t)b * 64 * 65536;

    #pragma unroll
    for (int grp = 0; grp < 2; ++grp) {
        float acc[2][16];
        #pragma unroll
        for (int c2 = 0; c2 < 2; ++c2)
            #pragma unroll
            for (int e = 0; e < 16; ++e) acc[c2][e] = 0.f;

        const int kh0 = grp ? 0 : 1;
        const int khs = grp ? 2 : 3;

        #pragma unroll
        for (int kw = 0; kw < 3; ++kw) {
            const int cxi = 1 - (kw & 1);     // compile-time
            const int dj  = kw >> 1;          // compile-time

            #pragma unroll 1
            for (int kh = kh0; kh < 3; kh += khs) {
                const int t  = kh * 3 + kw;
                const int di = kh >> 1;
                const uint32_t ab = aoff + (uint32_t)(t * TAPS);
                const uint32_t bd = bbase0 + (uint32_t)((di * 17 + dj) * 144);
                const uint32_t* kt = kbase + t * 128;

                // kern (pre-packed dup half2) per nb
                uint32_t kh2[4];
                #pragma unroll
                for (int nb = 0; nb < 4; ++nb)
                    kh2[nb] = kt[(nb >> 1) * 16 + (nb & 1) * 8];

                #pragma unroll
                for (int kb = 0; kb < 4; ++kb) {
                    uint32_t A[4];
                    ldmx4(A, ab + (uint32_t)(kb * 32));
                    #pragma unroll
                    for (int nb = 0; nb < 4; ++nb) {
                        const uint32_t bofs =
                            (uint32_t)(((nb >> 1) * 17 + (nb & 1) * 8) * 144 + kb * 32);
                        uint32_t b0, b1;
                        ldmx2(b0, b1, bd + bofs);
                        b0 = hmul2u(b0, kh2[nb]);
                        b1 = hmul2u(b1, kh2[nb]);
                        mma16816(acc[cxi][nb * 4 + 0], acc[cxi][nb * 4 + 1],
                                 acc[cxi][nb * 4 + 2], acc[cxi][nb * 4 + 3],
                                 A, b0, b1);
                    }
                }
            }
        }

        // store strips for cy = grp
        #pragma unroll
        for (int nb = 0; nb < 4; ++nb) {
            const int qy = 2 * nq + (nb >> 1);
            const int qx = (nb & 1) * 8 + 2 * t4;
            const int h  = 2 * (Ty0 + qy) + grp;
            const int w0 = 2 * (Tx0 + qx);
            #pragma unroll
            for (int rh = 0; rh < 2; ++rh) {
                const int o  = ob + gq + rh * 8;
                const float bv = rh ? bias_hi : bias_lo;
                float4 v = make_float4(acc[0][nb * 4 + rh * 2]     + bv,
                                       acc[1][nb * 4 + rh * 2]     + bv,
                                       acc[0][nb * 4 + rh * 2 + 1] + bv,
                                       acc[1][nb * 4 + rh * 2 + 1] + bv);
                *(float4*)&obase[((size_t)o * 256 + h) * 256 + w0] = v;
            }
        }
    }
}

extern "C" void kernel_launch(void* const* d_in, const int* in_sizes, int n_in,
                              void* d_out, int out_size) {
    const float* x      = (const float*)d_in[0];
    const float* guide  = (const float*)d_in[1];
    const float* weight = (const float*)d_in[2];
    const float* bias   = (const float*)d_in[3];
    float* out = (float*)d_out;

    cudaFuncSetAttribute(pac_hmma, cudaFuncAttributeMaxDynamicSharedMemorySize,
                         SMEM_TOTAL);
    // pre-transpose x and W into device-global fp16 staging buffers
    pac_pre<<<544, 512>>>(x, weight);
    // 4 batches * 128 tiles (8x16 quads each) = 512 CTAs
    pac_hmma<<<512, 512, SMEM_TOTAL>>>(guide, bias, out);
}

// round 16
// speedup vs baseline: 1.2236x; 1.0447x over previous
#include <cuda_runtime.h>
#include <cuda_fp16.h>
#include <cstdint>

// ---------------------------------------------------------------------------
// PAC transposed conv via warp-level tensor cores (mma.sync, baseline PTX).
// R15 = R14 + persistent CTAs (296 = 2/SM) with dynamic tile stealing via a
// global atomic counter; W staged once per CTA, X/kern per stolen tile.
// For output (h,w): valid taps (kh,kw) have (h+kh) odd & (w+kw) odd.
// Per tap t, shift (di,dj)=(kh>>1,kw>>1):
//   D[o,px] += sum_c W[o,c,t] * (kern_t[px] * x[c, qy+di, qx+dj])
//   out[o, 2qy+cy, 2qx+cx] = bias[o] + D_{cy,cx}[o,px]
// kern_t = exp(-0.5*sum_g (guide[g,h+kh-1,w+kw-1]-guide[g,h,w])^2), 0-pad.
// Tile: 8x16 quads (px = qy*16+qx, 128 px), o = 64. 512 tiles total.
// ---------------------------------------------------------------------------

constexpr int SMX  = 0;                   // X: [y9][x17] rows of 144B = 22032
constexpr int SMW  = 22032;               // W: 9 taps, padded stride
constexpr int TAPS = 9360;                // 65*144: tap t at bank shift 4t
constexpr int SMK  = SMW + 9 * TAPS;      // 106272 ; kern [9][128] dup-half2
constexpr int SMN  = SMK + 1152 * 4;      // next-tile broadcast slot
constexpr int SMEM_TOTAL = SMN + 16;      // 110896 B

constexpr int GRID_MAIN = 296;            // 2 CTAs per SM, one wave
constexpr int NTILES    = 512;

// device-global staging buffers (written by pac_pre each launch)
__device__ __align__(16) __half g_xh[4u * 128 * 128 * 64];  // [b][y][x][c] fp16
__device__ __align__(16) __half g_wh[9 * 4680];             // smem image of W
__device__ int g_ctr;                                       // tile counter

__device__ __forceinline__ uint32_t s2u(const void* p) {
    uint32_t a;
    asm("{ .reg .u64 t; cvta.to.shared.u64 t, %1; cvt.u32.u64 %0, t; }"
        : "=r"(a) : "l"(p));
    return a;
}
__device__ __forceinline__ void ldmx4(uint32_t* r, uint32_t addr) {
    asm volatile("ldmatrix.sync.aligned.m8n8.x4.shared.b16 {%0,%1,%2,%3}, [%4];"
                 : "=r"(r[0]), "=r"(r[1]), "=r"(r[2]), "=r"(r[3]) : "r"(addr));
}
__device__ __forceinline__ void ldmx2(uint32_t& r0, uint32_t& r1, uint32_t addr) {
    asm volatile("ldmatrix.sync.aligned.m8n8.x2.shared.b16 {%0,%1}, [%2];"
                 : "=r"(r0), "=r"(r1) : "r"(addr));
}
__device__ __forceinline__ void mma16816(float& d0, float& d1, float& d2, float& d3,
                                         const uint32_t* a, uint32_t b0, uint32_t b1) {
    asm volatile(
        "mma.sync.aligned.m16n8k16.row.col.f32.f16.f16.f32 "
        "{%0,%1,%2,%3}, {%4,%5,%6,%7}, {%8,%9}, {%0,%1,%2,%3};"
        : "+f"(d0), "+f"(d1), "+f"(d2), "+f"(d3)
        : "r"(a[0]), "r"(a[1]), "r"(a[2]), "r"(a[3]), "r"(b0), "r"(b1));
}
__device__ __forceinline__ uint32_t hmul2u(uint32_t a, uint32_t b) {
    __half2 r = __hmul2(*(__half2*)&a, *(__half2*)&b);
    return *(uint32_t*)&r;
}

// ---------------------------------------------------------------------------
// Pre-kernel: CTAs 0..511 transpose x (b,y) slices into g_xh [b][y][x][c];
//             CTAs 512..543 build the padded fp16 W image + reset counter.
// ---------------------------------------------------------------------------
__global__ void __launch_bounds__(512)
pac_pre(const float* __restrict__ x, const float* __restrict__ wgt)
{
    const int blk = blockIdx.x, tid = threadIdx.x;
    if (blk < 512) {
        __shared__ __align__(16) __half tb[128 * 66];   // [x][c] padded
        const int b = blk >> 7, y = blk & 127;
        const float* xin = x + ((size_t)b * 64 * 128 + y) * 128;
        #pragma unroll
        for (int k = 0; k < 16; ++k) {
            int c  = k * 4 + (tid >> 7);
            int xx = tid & 127;
            tb[xx * 66 + c] = __float2half_rn(xin[(size_t)c * 16384 + xx]);
        }
        __syncthreads();
        __half* outp = g_xh + ((size_t)(b * 128 + y) * 128) * 64;
        #pragma unroll
        for (int v = 0; v < 2; ++v) {
            int j  = (tid * 2 + v) * 8;      // 8 halves per store
            int xx = j >> 6, c0 = j & 63;
            const uint32_t* src =
                (const uint32_t*)((const char*)tb + xx * 132 + c0 * 2);
            uint4 val = make_uint4(src[0], src[1], src[2], src[3]);
            *(uint4*)(outp + j) = val;
        }
    } else {
        if (blk == 512 && tid == 0) g_ctr = GRID_MAIN;   // reset every launch
        const int i0 = (blk - 512) * 1152;
        #pragma unroll
        for (int k = 0; k < 3; ++k) {
            int i = i0 + k * 512 + tid;
            if (i < i0 + 1152) {
                int t  = i % 9;
                int oc = i / 9;
                int o  = oc & 63, c = oc >> 6;
                g_wh[t * 4680 + o * 72 + c] = __float2half_rn(wgt[i]);
            }
        }
    }
}

__global__ void __launch_bounds__(512, 2)
pac_hmma(const float* __restrict__ g, const float* __restrict__ bias,
         float* __restrict__ out)
{
    extern __shared__ char sm[];
    const uint32_t smb = s2u(sm);
    const int tid = threadIdx.x;

    // --- stage W once per persistent CTA: flat vectorized copy
    {
        const uint4* wsrc = (const uint4*)g_wh;     // 84240 B = 5265 vec4
        for (int i = tid; i < 5265; i += 512)
            *(uint4*)(sm + SMW + i * 16) = wsrc[i];
    }

    // lane constants (tile-independent)
    const int wid  = tid >> 5, lane = tid & 31;
    const int mblk = wid >> 2, nq = wid & 3;
    const int ob   = mblk * 16;
    const int gq   = lane >> 2, t4 = lane & 3;   // D rows gq,gq+8; cols 2t4,2t4+1
    const int a_orow = ob + (lane & 7) + ((lane >> 3) & 1) * 8;
    const uint32_t aoff = smb + SMW + (uint32_t)(a_orow * 144 + (lane >> 4) * 16);
    const int bj   = lane & 7;
    const int bmat = (lane >> 3) & 1;
    const uint32_t bbase0 =
        smb + SMX + (uint32_t)(((2 * nq) * 17 + bj) * 144 + bmat * 16);
    const uint32_t* kbase = (const uint32_t*)(sm + SMK) + nq * 32 + (lane >> 2);
    const float bias_lo = __ldg(&bias[ob + gq]);
    const float bias_hi = __ldg(&bias[ob + gq + 8]);
    volatile int* sm_next = (volatile int*)(sm + SMN);

    int tile = blockIdx.x;
    while (tile < NTILES) {
        const int b   = tile >> 7;
        const int tl  = tile & 127;
        const int Ty0 = (tl >> 3) * 8;
        const int Tx0 = (tl & 7) * 16;

        // --- stage X: rows (y,xc) copied 16B-wise from pre-transposed g_xh
        const __half* xg = g_xh + (size_t)b * 128 * 128 * 64;
        for (int i = tid; i < 1224; i += 512) {     // 153 rows * 8 vec4
            int r = i >> 3, v = i & 7;
            int y = r / 17, xc = r - y * 17;
            int gy = Ty0 + y, gx = Tx0 + xc;
            uint4 val = make_uint4(0u, 0u, 0u, 0u);
            if (gy < 128 && gx < 128)
                val = *(const uint4*)(xg + (size_t)((gy * 128 + gx) << 6) + v * 8);
            *(uint4*)(sm + SMX + r * 144 + v * 16) = val;
        }
        // --- stage kern: [tap 9][px 128], duplicated half2 (uint32)
        {
            const float* gb = g + b * 3 * 65536;
            uint32_t* kernS = (uint32_t*)(sm + SMK);
            for (int v = tid; v < 1152; v += 512) {
                int t  = v >> 7, px = v & 127;
                int qy = px >> 4, qx = px & 15;
                int kh = t / 3, kw = t - kh * 3;
                int cy = 1 - (kh & 1), cx = 1 - (kw & 1);
                int h  = 2 * (Ty0 + qy) + cy;
                int w  = 2 * (Tx0 + qx) + cx;
                int yy = h + kh - 1, xx = w + kw - 1;
                bool inb = ((unsigned)yy < 256u) & ((unsigned)xx < 256u);
                float s = 0.f;
                #pragma unroll
                for (int gg = 0; gg < 3; ++gg) {
                    float gc = __ldg(&gb[gg * 65536 + h * 256 + w]);
                    float gn = inb ? __ldg(&gb[gg * 65536 + yy * 256 + xx]) : 0.f;
                    float d = gn - gc;
                    s = fmaf(d, d, s);
                }
                __half2 hv = __float2half2_rn(__expf(-0.5f * s));
                kernS[v] = *(uint32_t*)&hv;
            }
        }
        __syncthreads();          // staging (incl. W on first iter) visible

        // fetch next tile id early; latency hides under the mainloop
        if (tid == 0) *sm_next = atomicAdd(&g_ctr, 1);

        float* obase = out + (size_t)b * 64 * 65536;

        #pragma unroll
        for (int grp = 0; grp < 2; ++grp) {
            float acc[2][16];
            #pragma unroll
            for (int c2 = 0; c2 < 2; ++c2)
                #pragma unroll
                for (int e = 0; e < 16; ++e) acc[c2][e] = 0.f;

            const int kh0 = grp ? 0 : 1;
            const int khs = grp ? 2 : 3;

            #pragma unroll
            for (int kw = 0; kw < 3; ++kw) {
                const int cxi = 1 - (kw & 1);     // compile-time
                const int dj  = kw >> 1;          // compile-time

                #pragma unroll 1
                for (int kh = kh0; kh < 3; kh += khs) {
                    const int t  = kh * 3 + kw;
                    const int di = kh >> 1;
                    const uint32_t ab = aoff + (uint32_t)(t * TAPS);
                    const uint32_t bd = bbase0 + (uint32_t)((di * 17 + dj) * 144);
                    const uint32_t* kt = kbase + t * 128;

                    uint32_t kh2[4];
                    #pragma unroll
                    for (int nb = 0; nb < 4; ++nb)
                        kh2[nb] = kt[(nb >> 1) * 16 + (nb & 1) * 8];

                    #pragma unroll
                    for (int kb = 0; kb < 4; ++kb) {
                        uint32_t A[4];
                        ldmx4(A, ab + (uint32_t)(kb * 32));
                        #pragma unroll
                        for (int nb = 0; nb < 4; ++nb) {
                            const uint32_t bofs =
                                (uint32_t)(((nb >> 1) * 17 + (nb & 1) * 8) * 144 + kb * 32);
                            uint32_t b0, b1;
                            ldmx2(b0, b1, bd + bofs);
                            b0 = hmul2u(b0, kh2[nb]);
                            b1 = hmul2u(b1, kh2[nb]);
                            mma16816(acc[cxi][nb * 4 + 0], acc[cxi][nb * 4 + 1],
                                     acc[cxi][nb * 4 + 2], acc[cxi][nb * 4 + 3],
                                     A, b0, b1);
                        }
                    }
                }
            }

            // store strips for cy = grp
            #pragma unroll
            for (int nb = 0; nb < 4; ++nb) {
                const int qy = 2 * nq + (nb >> 1);
                const int qx = (nb & 1) * 8 + 2 * t4;
                const int h  = 2 * (Ty0 + qy) + grp;
                const int w0 = 2 * (Tx0 + qx);
                #pragma unroll
                for (int rh = 0; rh < 2; ++rh) {
                    const int o  = ob + gq + rh * 8;
                    const float bv = rh ? bias_hi : bias_lo;
                    float4 v = make_float4(acc[0][nb * 4 + rh * 2]     + bv,
                                           acc[1][nb * 4 + rh * 2]     + bv,
                                           acc[0][nb * 4 + rh * 2 + 1] + bv,
                                           acc[1][nb * 4 + rh * 2 + 1] + bv);
                    *(float4*)&obase[((size_t)o * 256 + h) * 256 + w0] = v;
                }
            }
        }

        __syncthreads();          // mainloop smem reads done; sm_next visible
        tile = *sm_next;
    }
}

extern "C" void kernel_launch(void* const* d_in, const int* in_sizes, int n_in,
                              void* d_out, int out_size) {
    const float* x      = (const float*)d_in[0];
    const float* guide  = (const float*)d_in[1];
    const float* weight = (const float*)d_in[2];
    const float* bias   = (const float*)d_in[3];
    float* out = (float*)d_out;

    cudaFuncSetAttribute(pac_hmma, cudaFuncAttributeMaxDynamicSharedMemorySize,
                         SMEM_TOTAL);
    // pre-transpose x and W into device-global fp16 staging; reset counter
    pac_pre<<<544, 512>>>(x, weight);
    // persistent main kernel: 296 CTAs (2/SM), dynamic tile stealing
    pac_hmma<<<GRID_MAIN, 512, SMEM_TOTAL>>>(guide, bias, out);
}

// round 17
// speedup vs baseline: 1.2999x; 1.0624x over previous
#include <cuda_runtime.h>
#include <cuda_fp16.h>
#include <cstdint>

// ---------------------------------------------------------------------------
// PAC transposed conv via warp-level tensor cores (mma.sync, baseline PTX).
// R16 = R15 (persistent stealing) + lean shared-raw-B for kw in {0,1}:
// per kh, B loaded once and scaled by two kern values (kern via per-nb LDS,
// no cached kern arrays -> stays inside the 64-reg / 2-CTA equilibrium).
// For output (h,w): valid taps (kh,kw) have (h+kh) odd & (w+kw) odd.
// Per tap t, shift (di,dj)=(kh>>1,kw>>1):
//   D[o,px] += sum_c W[o,c,t] * (kern_t[px] * x[c, qy+di, qx+dj])
//   out[o, 2qy+cy, 2qx+cx] = bias[o] + D_{cy,cx}[o,px]
// kern_t = exp(-0.5*sum_g (guide[g,h+kh-1,w+kw-1]-guide[g,h,w])^2), 0-pad.
// Tile: 8x16 quads (px = qy*16+qx, 128 px), o = 64. 512 tiles total.
// ---------------------------------------------------------------------------

constexpr int SMX  = 0;                   // X: [y9][x17] rows of 144B = 22032
constexpr int SMW  = 22032;               // W: 9 taps, padded stride
constexpr int TAPS = 9360;                // 65*144: tap t at bank shift 4t
constexpr int SMK  = SMW + 9 * TAPS;      // 106272 ; kern [9][128] dup-half2
constexpr int SMN  = SMK + 1152 * 4;      // next-tile broadcast slot
constexpr int SMEM_TOTAL = SMN + 16;      // 110896 B

constexpr int GRID_MAIN = 296;            // 2 CTAs per SM, one wave
constexpr int NTILES    = 512;

// device-global staging buffers (written by pac_pre each launch)
__device__ __align__(16) __half g_xh[4u * 128 * 128 * 64];  // [b][y][x][c] fp16
__device__ __align__(16) __half g_wh[9 * 4680];             // smem image of W
__device__ int g_ctr;                                       // tile counter

__device__ __forceinline__ uint32_t s2u(const void* p) {
    uint32_t a;
    asm("{ .reg .u64 t; cvta.to.shared.u64 t, %1; cvt.u32.u64 %0, t; }"
        : "=r"(a) : "l"(p));
    return a;
}
__device__ __forceinline__ void ldmx4(uint32_t* r, uint32_t addr) {
    asm volatile("ldmatrix.sync.aligned.m8n8.x4.shared.b16 {%0,%1,%2,%3}, [%4];"
                 : "=r"(r[0]), "=r"(r[1]), "=r"(r[2]), "=r"(r[3]) : "r"(addr));
}
__device__ __forceinline__ void ldmx2(uint32_t& r0, uint32_t& r1, uint32_t addr) {
    asm volatile("ldmatrix.sync.aligned.m8n8.x2.shared.b16 {%0,%1}, [%2];"
                 : "=r"(r0), "=r"(r1) : "r"(addr));
}
__device__ __forceinline__ void mma16816(float& d0, float& d1, float& d2, float& d3,
                                         const uint32_t* a, uint32_t b0, uint32_t b1) {
    asm volatile(
        "mma.sync.aligned.m16n8k16.row.col.f32.f16.f16.f32 "
        "{%0,%1,%2,%3}, {%4,%5,%6,%7}, {%8,%9}, {%0,%1,%2,%3};"
        : "+f"(d0), "+f"(d1), "+f"(d2), "+f"(d3)
        : "r"(a[0]), "r"(a[1]), "r"(a[2]), "r"(a[3]), "r"(b0), "r"(b1));
}
__device__ __forceinline__ uint32_t hmul2u(uint32_t a, uint32_t b) {
    __half2 r = __hmul2(*(__half2*)&a, *(__half2*)&b);
    return *(uint32_t*)&r;
}

// ---------------------------------------------------------------------------
// Pre-kernel: CTAs 0..511 transpose x (b,y) slices into g_xh [b][y][x][c];
//             CTAs 512..543 build the padded fp16 W image + reset counter.
// ---------------------------------------------------------------------------
__global__ void __launch_bounds__(512)
pac_pre(const float* __restrict__ x, const float* __restrict__ wgt)
{
    const int blk = blockIdx.x, tid = threadIdx.x;
    if (blk < 512) {
        __shared__ __align__(16) __half tb[128 * 66];   // [x][c] padded
        const int b = blk >> 7, y = blk & 127;
        const float* xin = x + ((size_t)b * 64 * 128 + y) * 128;
        #pragma unroll
        for (int k = 0; k < 16; ++k) {
            int c  = k * 4 + (tid >> 7);
            int xx = tid & 127;
            tb[xx * 66 + c] = __float2half_rn(xin[(size_t)c * 16384 + xx]);
        }
        __syncthreads();
        __half* outp = g_xh + ((size_t)(b * 128 + y) * 128) * 64;
        #pragma unroll
        for (int v = 0; v < 2; ++v) {
            int j  = (tid * 2 + v) * 8;      // 8 halves per store
            int xx = j >> 6, c0 = j & 63;
            const uint32_t* src =
                (const uint32_t*)((const char*)tb + xx * 132 + c0 * 2);
            uint4 val = make_uint4(src[0], src[1], src[2], src[3]);
            *(uint4*)(outp + j) = val;
        }
    } else {
        if (blk == 512 && tid == 0) g_ctr = GRID_MAIN;   // reset every launch
        const int i0 = (blk - 512) * 1152;
        #pragma unroll
        for (int k = 0; k < 3; ++k) {
            int i = i0 + k * 512 + tid;
            if (i < i0 + 1152) {
                int t  = i % 9;
                int oc = i / 9;
                int o  = oc & 63, c = oc >> 6;
                g_wh[t * 4680 + o * 72 + c] = __float2half_rn(wgt[i]);
            }
        }
    }
}

__global__ void __launch_bounds__(512, 2)
pac_hmma(const float* __restrict__ g, const float* __restrict__ bias,
         float* __restrict__ out)
{
    extern __shared__ char sm[];
    const uint32_t smb = s2u(sm);
    const int tid = threadIdx.x;

    // --- stage W once per persistent CTA: flat vectorized copy
    {
        const uint4* wsrc = (const uint4*)g_wh;     // 84240 B = 5265 vec4
        for (int i = tid; i < 5265; i += 512)
            *(uint4*)(sm + SMW + i * 16) = wsrc[i];
    }

    // lane constants (tile-independent)
    const int wid  = tid >> 5, lane = tid & 31;
    const int mblk = wid >> 2, nq = wid & 3;
    const int ob   = mblk * 16;
    const int gq   = lane >> 2, t4 = lane & 3;   // D rows gq,gq+8; cols 2t4,2t4+1
    const int a_orow = ob + (lane & 7) + ((lane >> 3) & 1) * 8;
    const uint32_t aoff = smb + SMW + (uint32_t)(a_orow * 144 + (lane >> 4) * 16);
    const int bj   = lane & 7;
    const int bmat = (lane >> 3) & 1;
    const uint32_t bbase0 =
        smb + SMX + (uint32_t)(((2 * nq) * 17 + bj) * 144 + bmat * 16);
    const uint32_t* kbase = (const uint32_t*)(sm + SMK) + nq * 32 + (lane >> 2);
    const float bias_lo = __ldg(&bias[ob + gq]);
    const float bias_hi = __ldg(&bias[ob + gq + 8]);
    volatile int* sm_next = (volatile int*)(sm + SMN);

    int tile = blockIdx.x;
    while (tile < NTILES) {
        const int b   = tile >> 7;
        const int tl  = tile & 127;
        const int Ty0 = (tl >> 3) * 8;
        const int Tx0 = (tl & 7) * 16;

        // --- stage X: rows (y,xc) copied 16B-wise from pre-transposed g_xh
        const __half* xg = g_xh + (size_t)b * 128 * 128 * 64;
        for (int i = tid; i < 1224; i += 512) {     // 153 rows * 8 vec4
            int r = i >> 3, v = i & 7;
            int y = r / 17, xc = r - y * 17;
            int gy = Ty0 + y, gx = Tx0 + xc;
            uint4 val = make_uint4(0u, 0u, 0u, 0u);
            if (gy < 128 && gx < 128)
                val = *(const uint4*)(xg + (size_t)((gy * 128 + gx) << 6) + v * 8);
            *(uint4*)(sm + SMX + r * 144 + v * 16) = val;
        }
        // --- stage kern: [tap 9][px 128], duplicated half2 (uint32)
        {
            const float* gb = g + b * 3 * 65536;
            uint32_t* kernS = (uint32_t*)(sm + SMK);
            for (int v = tid; v < 1152; v += 512) {
                int t  = v >> 7, px = v & 127;
                int qy = px >> 4, qx = px & 15;
                int kh = t / 3, kw = t - kh * 3;
                int cy = 1 - (kh & 1), cx = 1 - (kw & 1);
                int h  = 2 * (Ty0 + qy) + cy;
                int w  = 2 * (Tx0 + qx) + cx;
                int yy = h + kh - 1, xx = w + kw - 1;
                bool inb = ((unsigned)yy < 256u) & ((unsigned)xx < 256u);
                float s = 0.f;
                #pragma unroll
                for (int gg = 0; gg < 3; ++gg) {
                    float gc = __ldg(&gb[gg * 65536 + h * 256 + w]);
                    float gn = inb ? __ldg(&gb[gg * 65536 + yy * 256 + xx]) : 0.f;
                    float d = gn - gc;
                    s = fmaf(d, d, s);
                }
                __half2 hv = __float2half2_rn(__expf(-0.5f * s));
                kernS[v] = *(uint32_t*)&hv;
            }
        }
        __syncthreads();          // staging (incl. W on first iter) visible

        // fetch next tile id early; latency hides under the mainloop
        if (tid == 0) *sm_next = atomicAdd(&g_ctr, 1);

        float* obase = out + (size_t)b * 64 * 65536;

        #pragma unroll
        for (int grp = 0; grp < 2; ++grp) {
            float acc[2][16];
            #pragma unroll
            for (int c2 = 0; c2 < 2; ++c2)
                #pragma unroll
                for (int e = 0; e < 16; ++e) acc[c2][e] = 0.f;

            const int kh0 = grp ? 0 : 1;
            const int khs = grp ? 2 : 3;

            #pragma unroll 1
            for (int kh = kh0; kh < 3; kh += khs) {
                const int t0 = kh * 3;             // kw=0 tap
                const uint32_t ab0 = aoff + (uint32_t)(t0 * TAPS);
                const uint32_t bd  = bbase0 + (uint32_t)(((kh >> 1) * 17) * 144);
                const uint32_t* kt = kbase + t0 * 128;

                // --- fused pass: kw=0 (-> acc[1]) and kw=1 (-> acc[0])
                //     share raw B (dj=0); kern loaded per-nb (2 LDS.32)
                #pragma unroll
                for (int kb = 0; kb < 4; ++kb) {
                    uint32_t A0[4], A1[4];
                    ldmx4(A0, ab0 + (uint32_t)(kb * 32));
                    ldmx4(A1, ab0 + (uint32_t)(TAPS + kb * 32));
                    #pragma unroll
                    for (int nb = 0; nb < 4; ++nb) {
                        const int ko = (nb >> 1) * 16 + (nb & 1) * 8;
                        const uint32_t bofs =
                            (uint32_t)(((nb >> 1) * 17 + (nb & 1) * 8) * 144 + kb * 32);
                        uint32_t r0, r1;
                        ldmx2(r0, r1, bd + bofs);
                        uint32_t kv = kt[ko];            // kern tap (kh,0)
                        uint32_t b0 = hmul2u(r0, kv);
                        uint32_t b1 = hmul2u(r1, kv);
                        mma16816(acc[1][nb * 4 + 0], acc[1][nb * 4 + 1],
                                 acc[1][nb * 4 + 2], acc[1][nb * 4 + 3],
                                 A0, b0, b1);
                        kv = kt[128 + ko];               // kern tap (kh,1)
                        b0 = hmul2u(r0, kv);
                        b1 = hmul2u(r1, kv);
                        mma16816(acc[0][nb * 4 + 0], acc[0][nb * 4 + 1],
                                 acc[0][nb * 4 + 2], acc[0][nb * 4 + 3],
                                 A1, b0, b1);
                    }
                }
                // --- kw=2 pass: dj=1, own B (-> acc[1])
                #pragma unroll
                for (int kb = 0; kb < 4; ++kb) {
                    uint32_t A2[4];
                    ldmx4(A2, ab0 + (uint32_t)(2 * TAPS + kb * 32));
                    #pragma unroll
                    for (int nb = 0; nb < 4; ++nb) {
                        const int ko = (nb >> 1) * 16 + (nb & 1) * 8;
                        const uint32_t bofs =
                            (uint32_t)(((nb >> 1) * 17 + (nb & 1) * 8) * 144 + kb * 32);
                        uint32_t r0, r1;
                        ldmx2(r0, r1, bd + 144 + bofs);   // dj=1
                        uint32_t kv = kt[256 + ko];       // kern tap (kh,2)
                        uint32_t b0 = hmul2u(r0, kv);
                        uint32_t b1 = hmul2u(r1, kv);
                        mma16816(acc[1][nb * 4 + 0], acc[1][nb * 4 + 1],
                                 acc[1][nb * 4 + 2], acc[1][nb * 4 + 3],
                                 A2, b0, b1);
                    }
                }
            }

            // store strips for cy = grp
            #pragma unroll
            for (int nb = 0; nb < 4; ++nb) {
                const int qy = 2 * nq + (nb >> 1);
                const int qx = (nb & 1) * 8 + 2 * t4;
                const int h  = 2 * (Ty0 + qy) + grp;
                const int w0 = 2 * (Tx0 + qx);
                #pragma unroll
                for (int rh = 0; rh < 2; ++rh) {
                    const int o  = ob + gq + rh * 8;
                    const float bv = rh ? bias_hi : bias_lo;
                    float4 v = make_float4(acc[0][nb * 4 + rh * 2]     + bv,
                                           acc[1][nb * 4 + rh * 2]     + bv,
                                           acc[0][nb * 4 + rh * 2 + 1] + bv,
                                           acc[1][nb * 4 + rh * 2 + 1] + bv);
                    *(float4*)&obase[((size_t)o * 256 + h) * 256 + w0] = v;
                }
            }
        }

        __syncthreads();          // mainloop smem reads done; sm_next visible
        tile = *sm_next;
    }
}

extern "C" void kernel_launch(void* const* d_in, const int* in_sizes, int n_in,
                              void* d_out, int out_size) {
    const float* x      = (const float*)d_in[0];
    const float* guide  = (const float*)d_in[1];
    const float* weight = (const float*)d_in[2];
    const float* bias   = (const float*)d_in[3];
    float* out = (float*)d_out;

    cudaFuncSetAttribute(pac_hmma, cudaFuncAttributeMaxDynamicSharedMemorySize,
                         SMEM_TOTAL);
    // pre-transpose x and W into device-global fp16 staging; reset counter
    pac_pre<<<544, 512>>>(x, weight);
    // persistent main kernel: 296 CTAs (2/SM), dynamic tile stealing
    pac_hmma<<<GRID_MAIN, 512, SMEM_TOTAL>>>(guide, bias, out);
}